// round 13
// baseline (speedup 1.0000x reference)
#include <cuda_runtime.h>
#include <cuda_bf16.h>

// Problem shape (fixed by dataset):
//   S = 8192  source codes
//   G = 1024  groups
//   T = 4096  time segments (t0 sorted ascending)
//   E = 16384 events
//
// out[t, g] = sum over events with start <= t0[t] < end of
//             rate[e] * weights[index[e]], grouped by group_id[index[e]].
//
// t0 sorted -> each event is two difference-array endpoints (+w at lo, -w
// at hi). SINGLE persistent kernel (1 graph node; rounds 4-12 showed the
// 23us plateau was dominated by ~2.5-3.5us/node boundary overhead):
//   Phase 1: binary search per event; bucket endpoint records per 32-row
//            chunk + REDG chunk column sums into g_part[g][c].
//   -- grid barrier --
//   Phase 2: warp-per-column shuffle scan of g_part (zero-restoring it)
//            -> exclusive offsets g_off[g][c]; block 0 snapshots/resets
//            the bucket counters.
//   -- grid barrier --
//   Phase 3: block = chunk; rebuild 32x256 diff tiles in smem from the
//            chunk's records (4 column-quarters), prefix seeded by g_off,
//            write the output tile once. No 16MB zero, no 16MB re-read.

#define T_DIM  4096
#define G_DIM  1024
#define NCH    128            // 32-row chunks
#define CHROWS 32
#define CAP    1024           // records per chunk (expected ~256, sigma ~16)
#define GRID   128
#define NTHR   256

// Bank-conflict-breaking bijection on [0,4096): x ^ (x>>5) ^ (x>>10)
#define SWZ(m) ((m) ^ ((m) >> 5) ^ ((m) >> 10))

__device__ unsigned g_bar = 0;               // monotonic barrier counter
__device__ int   g_cnt[NCH];                 // bucket counts (zero-invariant)
__device__ int   g_cnt2[NCH];                // snapshot for phase 3
__device__ uint2 g_rec[NCH][CAP];            // endpoint records, 1 MB
__device__ float g_part[G_DIM][NCH];         // chunk sums (zero-invariant)
__device__ float g_off[G_DIM][NCH];          // exclusive offsets

// Monotonic-generation grid barrier: no reset -> safe across graph replays.
__device__ __forceinline__ void grid_barrier()
{
    __syncthreads();
    if (threadIdx.x == 0) {
        __threadfence();                               // release
        unsigned old = atomicAdd(&g_bar, 1u);
        unsigned target = (old / GRID + 1u) * GRID;
        while (atomicAdd(&g_bar, 0u) < target)
            __nanosleep(64);
        __threadfence();                               // acquire
    }
    __syncthreads();
}

__global__ void __launch_bounds__(NTHR)
fused_kernel(const int* __restrict__ index,
             const float* __restrict__ rate,
             const float* __restrict__ starttime,
             const float* __restrict__ endtime,
             const float* __restrict__ t0,
             const int* __restrict__ group_id,
             const float* __restrict__ weights,
             float* __restrict__ out,
             int E)
{
    __shared__ float smem_buf[CHROWS * 256];   // 32KB: t0 (phase1) / tile (phase3)
    int tid = threadIdx.x;
    int bid = blockIdx.x;

    // ---------------- Phase 1: search + bucket ----------------
    bool has_events = (bid * NTHR < E);
    if (has_events) {
        for (int i = tid; i < T_DIM; i += NTHR)
            smem_buf[SWZ(i)] = t0[i];

        // prefetch event data (overlaps the smem fill / LDS chains)
        int e = bid * NTHR + tid;
        float st = 0.f, en = 0.f, w = 0.f;
        int g = 0;
        bool valid = (e < E);
        if (valid) {
            st = starttime[e];
            en = endtime[e];
            int src = index[e];
            w  = rate[e] * weights[src];
            g  = group_id[src];
        }
        __syncthreads();

        if (valid) {
            // two exact lower_bounds, interleaved for ILP-2
            int lo = 0, hi = T_DIM, lo2 = 0, hi2 = T_DIM;
            while (lo < hi && lo2 < hi2) {
                int m1 = (lo + hi) >> 1;
                int m2 = (lo2 + hi2) >> 1;
                float a = smem_buf[SWZ(m1)];
                float b = smem_buf[SWZ(m2)];
                if (a < st) lo = m1 + 1; else hi = m1;
                if (b < en) lo2 = m2 + 1; else hi2 = m2;
            }
            while (lo < hi) {
                int m = (lo + hi) >> 1;
                if (smem_buf[SWZ(m)] < st) lo = m + 1; else hi = m;
            }
            while (lo2 < hi2) {
                int m = (lo2 + hi2) >> 1;
                if (smem_buf[SWZ(m)] < en) lo2 = m + 1; else hi2 = m;
            }
            // active time-index range [lo, lo2)
            if (lo < lo2) {
                {   // +w endpoint
                    int c = lo >> 5, r = lo & 31;
                    int pos = atomicAdd(&g_cnt[c], 1);
                    if (pos < CAP) {
                        atomicAdd(&g_part[g][c], w);
                        g_rec[c][pos] = make_uint2((unsigned)((r << 10) | g),
                                                   __float_as_uint(w));
                    }
                }
                if (lo2 < T_DIM) {   // -w endpoint
                    int c = lo2 >> 5, r = lo2 & 31;
                    int pos = atomicAdd(&g_cnt[c], 1);
                    if (pos < CAP) {
                        atomicAdd(&g_part[g][c], -w);
                        g_rec[c][pos] = make_uint2((unsigned)((r << 10) | g),
                                                   __float_as_uint(-w));
                    }
                }
            }
        }
    }

    grid_barrier();

    // ---------------- Phase 2: column scan of chunk sums ----------------
    {
        int warp = tid >> 5;
        int lane = tid & 31;
        int g = bid * (NTHR / 32) + warp;          // 128 blocks * 8 warps = 1024

        // lane owns chunks [lane*4, lane*4+4): one float4
        float4* base = (float4*)&g_part[g][lane * 4];
        float4 x = *base;
        *base = make_float4(0.f, 0.f, 0.f, 0.f);   // restore zero invariant

        float tot = x.x + x.y + x.z + x.w;
        float acc = tot;
        #pragma unroll
        for (int off = 1; off < 32; off <<= 1) {
            float up = __shfl_up_sync(0xFFFFFFFFu, acc, off);
            if (lane >= off) acc += up;
        }
        float run = acc - tot;                     // exclusive prefix of lane sums

        float4 o;
        o.x = run;  run += x.x;
        o.y = run;  run += x.y;
        o.z = run;  run += x.z;
        o.w = run;
        *(float4*)&g_off[g][lane * 4] = o;

        // block 0 snapshots + resets bucket counts
        if (bid == 0 && tid < NCH) {
            g_cnt2[tid] = g_cnt[tid];
            g_cnt[tid] = 0;
        }
    }

    grid_barrier();

    // ---------------- Phase 3: rebuild + prefix + write ----------------
    {
        int c = bid;                               // chunk 0..127
        int n = g_cnt2[c];
        if (n > CAP) n = CAP;

        #pragma unroll 1
        for (int q = 0; q < 4; q++) {              // column quarters of 256
            __syncthreads();
            // zero the 32x256 tile
            float4* t4 = (float4*)smem_buf;
            #pragma unroll
            for (int i = 0; i < 8; i++)
                t4[i * NTHR + tid] = make_float4(0.f, 0.f, 0.f, 0.f);
            __syncthreads();

            // scatter this chunk's records for this quarter
            for (int i = tid; i < n; i += NTHR) {
                uint2 rec = g_rec[c][i];
                int g = rec.x & 1023;
                if ((g >> 8) == q) {
                    int r = rec.x >> 10;
                    atomicAdd(&smem_buf[r * 256 + (g & 255)],
                              __uint_as_float(rec.y));
                }
            }
            __syncthreads();

            // running prefix down 32 rows, seeded by the chunk offset
            int col = q * 256 + tid;
            float run = g_off[col][c];
            float* dst = out + (size_t)c * CHROWS * G_DIM + col;
            #pragma unroll
            for (int r = 0; r < CHROWS; r++) {
                run += smem_buf[r * 256 + tid];
                dst[r * G_DIM] = run;
            }
        }
    }
}

// ---------------------------------------------------------------------------
extern "C" void kernel_launch(void* const* d_in, const int* in_sizes, int n_in,
                              void* d_out, int out_size)
{
    const int*   index     = (const int*)  d_in[0];
    const float* rate      = (const float*)d_in[1];
    const float* starttime = (const float*)d_in[2];
    const float* endtime   = (const float*)d_in[3];
    const float* t0        = (const float*)d_in[4];
    const int*   group_id  = (const int*)  d_in[5];
    const float* weights   = (const float*)d_in[6];

    int E = in_sizes[0];

    fused_kernel<<<GRID, NTHR>>>(index, rate, starttime, endtime,
                                 t0, group_id, weights, (float*)d_out, E);
}

// round 14
// speedup vs baseline: 1.0103x; 1.0103x over previous
#include <cuda_runtime.h>
#include <cuda_bf16.h>

// Problem shape (fixed by dataset):
//   S = 8192, G = 1024, T = 4096 (t0 sorted), E = 16384
//
// out[t, g] = sum over events with start <= t0[t] < end of
//             rate[e] * weights[index[e]], grouped by group_id[index[e]].
//
// Single persistent kernel, difference-array formulation:
//   Phase 1: binary search per event; endpoint records bucketed per 8-row
//            chunk (512 chunks) + REDG chunk column sums g_part[g][c].
//   Phase 2: warp-per-column shuffle scan of g_part -> exclusive offsets,
//            transposed through smem into chunk-major g_off[c][g];
//            restores all scratch zero-invariants for graph replay.
//   Phase 3: block = 2 chunks; rebuild 8x1024 diff tile in smem from the
//            chunk's records, 8-deep prefix seeded by coalesced g_off
//            read, one coalesced float4 output write. Output touched ONCE;
//            all other traffic is L2/smem-resident.

#define T_DIM  4096
#define G_DIM  1024
#define NCH    512            // 8-row chunks
#define CHROWS 8
#define CAP    256            // records per chunk (expected ~64, sigma ~8)
#define GRID   256
#define NTHR   256

// Bank-conflict-breaking bijection on [0,4096): x ^ (x>>5) ^ (x>>10)
#define SWZ(m) ((m) ^ ((m) >> 5) ^ ((m) >> 10))

__device__ unsigned g_bar = 0;           // monotonic barrier counter
__device__ int   g_cnt[NCH];             // bucket counts (zero-invariant)
__device__ int   g_cnt2[NCH];            // snapshot for phase 3
__device__ uint2 g_rec[NCH][CAP];        // endpoint records, 1 MB
__device__ float g_part[G_DIM][NCH];     // chunk sums (zero-invariant), 2 MB
__device__ float g_off[NCH][G_DIM];      // exclusive offsets, chunk-major, 2 MB

// Monotonic-generation grid barrier: no reset -> safe across graph replays.
__device__ __forceinline__ void grid_barrier()
{
    __syncthreads();
    __threadfence();                                   // release (all threads)
    if (threadIdx.x == 0) {
        unsigned old = atomicAdd(&g_bar, 1u);
        unsigned target = (old / GRID + 1u) * GRID;
        while (atomicAdd(&g_bar, 0u) < target)
            __nanosleep(32);
    }
    __syncthreads();
    __threadfence();                                   // acquire
}

__global__ void __launch_bounds__(NTHR)
fused_kernel(const int* __restrict__ index,
             const float* __restrict__ rate,
             const float* __restrict__ starttime,
             const float* __restrict__ endtime,
             const float* __restrict__ t0,
             const int* __restrict__ group_id,
             const float* __restrict__ weights,
             float* __restrict__ out,
             int E)
{
    __shared__ float smem_buf[CHROWS * G_DIM];  // 32 KB, reused per phase
    int tid = threadIdx.x;
    int bid = blockIdx.x;

    // ---------------- Phase 1: search + bucket ----------------
    if (bid * NTHR < E) {
        for (int i = tid; i < T_DIM; i += NTHR)
            smem_buf[SWZ(i)] = t0[i];

        int e = bid * NTHR + tid;
        float st = 0.f, en = 0.f, w = 0.f;
        int g = 0;
        bool valid = (e < E);
        if (valid) {
            st = starttime[e];
            en = endtime[e];
            int src = index[e];
            w  = rate[e] * weights[src];
            g  = group_id[src];
        }
        __syncthreads();

        if (valid) {
            // two exact lower_bounds, interleaved for ILP-2
            int lo = 0, hi = T_DIM, lo2 = 0, hi2 = T_DIM;
            while (lo < hi && lo2 < hi2) {
                int m1 = (lo + hi) >> 1;
                int m2 = (lo2 + hi2) >> 1;
                float a = smem_buf[SWZ(m1)];
                float b = smem_buf[SWZ(m2)];
                if (a < st) lo = m1 + 1; else hi = m1;
                if (b < en) lo2 = m2 + 1; else hi2 = m2;
            }
            while (lo < hi) {
                int m = (lo + hi) >> 1;
                if (smem_buf[SWZ(m)] < st) lo = m + 1; else hi = m;
            }
            while (lo2 < hi2) {
                int m = (lo2 + hi2) >> 1;
                if (smem_buf[SWZ(m)] < en) lo2 = m + 1; else hi2 = m;
            }
            if (lo < lo2) {                   // active range [lo, lo2)
                {
                    int c = lo >> 3, r = lo & 7;
                    int pos = atomicAdd(&g_cnt[c], 1);
                    if (pos < CAP) {
                        atomicAdd(&g_part[g][c], w);
                        g_rec[c][pos] = make_uint2((unsigned)((r << 10) | g),
                                                   __float_as_uint(w));
                    }
                }
                if (lo2 < T_DIM) {
                    int c = lo2 >> 3, r = lo2 & 7;
                    int pos = atomicAdd(&g_cnt[c], 1);
                    if (pos < CAP) {
                        atomicAdd(&g_part[g][c], -w);
                        g_rec[c][pos] = make_uint2((unsigned)((r << 10) | g),
                                                   __float_as_uint(-w));
                    }
                }
            }
        }
    }

    grid_barrier();

    // ---------------- Phase 2: column scan + transpose ----------------
    // Blocks 0..127: 8 warps each, warp = one group column g over 512 chunks.
    if (bid < 128) {
        int warp = tid >> 5;
        int lane = tid & 31;
        int gbase = bid * 8;
        int g = gbase + warp;

        // lane owns chunks [lane*16, lane*16+16)
        float4* base = (float4*)&g_part[g][lane * 16];
        float v[16];
        #pragma unroll
        for (int q = 0; q < 4; q++) {
            float4 x = base[q];
            v[q*4+0] = x.x; v[q*4+1] = x.y; v[q*4+2] = x.z; v[q*4+3] = x.w;
        }
        float4 z4 = make_float4(0.f, 0.f, 0.f, 0.f);
        #pragma unroll
        for (int q = 0; q < 4; q++) base[q] = z4;      // restore zero inv.

        float tot = 0.f;
        #pragma unroll
        for (int i = 0; i < 16; i++) tot += v[i];
        float acc = tot;
        #pragma unroll
        for (int off = 1; off < 32; off <<= 1) {
            float up = __shfl_up_sync(0xFFFFFFFFu, acc, off);
            if (lane >= off) acc += up;
        }
        float run = acc - tot;               // exclusive prefix of lane sums

        // stride-13 padded transpose tile: sh[c*13 + w], conflict-free
        #pragma unroll
        for (int i = 0; i < 16; i++) {
            smem_buf[(lane * 16 + i) * 13 + warp] = run;
            run += v[i];
        }
        __syncthreads();

        // coalesced-ish transposed write: thread t -> chunks 2t, 2t+1
        #pragma unroll
        for (int k = 0; k < 2; k++) {
            int c = tid * 2 + k;
            const float* row = &smem_buf[c * 13];
            *(float4*)&g_off[c][gbase]     = make_float4(row[0], row[1],
                                                         row[2], row[3]);
            *(float4*)&g_off[c][gbase + 4] = make_float4(row[4], row[5],
                                                         row[6], row[7]);
        }
    }
    // Blocks 0,1: snapshot + reset bucket counters (512 counters)
    if (bid < 2) {
        int c = bid * NTHR + tid;
        g_cnt2[c] = g_cnt[c];
        g_cnt[c] = 0;
    }

    grid_barrier();

    // ---------------- Phase 3: rebuild + prefix + write ----------------
    float4* t4 = (float4*)smem_buf;
    #pragma unroll 1
    for (int k = 0; k < 2; k++) {
        int c = bid * 2 + k;                 // chunk 0..511
        __syncthreads();
        // zero the 8x1024 tile (2048 float4)
        #pragma unroll
        for (int i = 0; i < 8; i++)
            t4[i * NTHR + tid] = make_float4(0.f, 0.f, 0.f, 0.f);
        __syncthreads();

        int n = g_cnt2[c];
        if (n > CAP) n = CAP;
        for (int i = tid; i < n; i += NTHR) {
            uint2 rec = g_rec[c][i];
            int r = rec.x >> 10;
            int g = rec.x & 1023;
            atomicAdd(&smem_buf[r * G_DIM + g], __uint_as_float(rec.y));
        }
        __syncthreads();

        // 8-deep running prefix seeded by coalesced chunk offset
        float4 run = *(const float4*)&g_off[c][4 * tid];
        float4* dst = (float4*)out + (size_t)c * CHROWS * (G_DIM / 4) + tid;
        #pragma unroll
        for (int r = 0; r < CHROWS; r++) {
            float4 v = t4[r * NTHR + tid];
            run.x += v.x; run.y += v.y; run.z += v.z; run.w += v.w;
            dst[r * (G_DIM / 4)] = run;
        }
    }
}

// ---------------------------------------------------------------------------
extern "C" void kernel_launch(void* const* d_in, const int* in_sizes, int n_in,
                              void* d_out, int out_size)
{
    const int*   index     = (const int*)  d_in[0];
    const float* rate      = (const float*)d_in[1];
    const float* starttime = (const float*)d_in[2];
    const float* endtime   = (const float*)d_in[3];
    const float* t0        = (const float*)d_in[4];
    const int*   group_id  = (const int*)  d_in[5];
    const float* weights   = (const float*)d_in[6];

    int E = in_sizes[0];

    fused_kernel<<<GRID, NTHR>>>(index, rate, starttime, endtime,
                                 t0, group_id, weights, (float*)d_out, E);
}